// round 9
// baseline (speedup 1.0000x reference)
#include <cuda_runtime.h>

// LSTM: B=512, T=1000, IN=39, H=64 (4H=256 gates), OUT=48.
// R8 = R7 + occupancy. Both kernels go to 512 threads (4 warps/SMSP):
//  - xproj_T: thread = (gate, bt-half of a 32-bt tile) -> 16 warps/SM,
//    LDS (~2496 wf/SM/tile) and FMA (~2496 cyc/SMSP/tile) floors overlap.
//  - lstm_rec: Phase A k-split 8 (weights 64 regs/thread), C1 k-split 8
//    (384 threads), B on 0-255 and C2 on 384-479 share the bar1-bar2
//    window. Same per-SM work as R7, issued from twice the warps.
// (R8 bench was an infra failure — container died before execution;
//  resubmitting unchanged after static resource audit: 39KB smem, ~110-125
//  regs at the 128 cap, no alloc/sync APIs.)

#define B_    512
#define T_    1000
#define IN_   39
#define H_    64
#define G_    256
#define OUT_  48
#define ROWS  4
#define CTAS  (B_/ROWS)   // 128
#define XTILE 32

typedef unsigned long long u64;

__device__ float g_xg[(size_t)B_ * T_ * G_];   // 512 MB x-projection scratch

__device__ __forceinline__ u64 fma2(u64 a, u64 b, u64 c) {
    u64 d;
    asm("fma.rn.f32x2 %0, %1, %2, %3;" : "=l"(d) : "l"(a), "l"(b), "l"(c));
    return d;
}
__device__ __forceinline__ u64 add2(u64 a, u64 b) {
    u64 d;
    asm("add.rn.f32x2 %0, %1, %2;" : "=l"(d) : "l"(a), "l"(b));
    return d;
}
__device__ __forceinline__ u64 pack2(float lo, float hi) {
    u64 d;
    asm("mov.b64 %0, {%1, %2};" : "=l"(d) : "f"(lo), "f"(hi));
    return d;
}
__device__ __forceinline__ void unpack2(u64 v, float &lo, float &hi) {
    asm("mov.b64 {%0, %1}, %2;" : "=f"(lo), "=f"(hi) : "l"(v));
}
__device__ __forceinline__ float sigm(float x) {
    return __fdividef(1.0f, 1.0f + __expf(-x));
}
__device__ __forceinline__ float tanh_(float x) {
    float e = __expf(2.0f * x);
    return 1.0f - __fdividef(2.0f, e + 1.0f);
}

// ====================== kernel 1: x projection (T-layout) ===================
// 512 threads: thread = (gate g, bt-half). Each handles 16 of the tile's 32
// bt rows: 156 broadcast LDS.128 + 312 FFMA2, weights dup'd in 78 regs.
__global__ void __launch_bounds__(512, 1)
xproj_T(const float* __restrict__ x,
        const float* __restrict__ W_ih,
        const float* __restrict__ b_ih,
        const float* __restrict__ b_hh)
{
    __shared__ __align__(16) float xT[IN_][XTILE];   // [k][bt]
    const int g   = threadIdx.x & 255;
    const int bth = threadIdx.x >> 8;                // 0/1: bt rows 16bth..16bth+15
    const size_t bt0 = (size_t)blockIdx.x * XTILE;

    u64 w[IN_];
    #pragma unroll
    for (int k = 0; k < IN_; k++) {
        float v = W_ih[g*IN_ + k];
        w[k] = pack2(v, v);
    }
    const float bias = b_ih[g] + b_hh[g];
    const u64 bias2 = pack2(bias, bias);

    for (int idx = threadIdx.x; idx < IN_*XTILE; idx += 512) {
        int r = idx & (XTILE-1), i = idx >> 5;
        xT[i][r] = x[(bt0 + r)*IN_ + i];
    }
    __syncthreads();

    u64 acc[8];
    #pragma unroll
    for (int p = 0; p < 8; p++) acc[p] = bias2;

    #pragma unroll
    for (int k = 0; k < IN_; k++) {
        const ulonglong2* xp = (const ulonglong2*)xT[k] + bth*4;
        const u64 wk = w[k];
        #pragma unroll
        for (int q = 0; q < 4; q++) {
            ulonglong2 v = xp[q];              // 4 bt rows of element k
            acc[2*q    ] = fma2(wk, v.x, acc[2*q    ]);
            acc[2*q + 1] = fma2(wk, v.y, acc[2*q + 1]);
        }
    }

    float* outp = g_xg + (bt0 + 16*bth) * G_ + g;   // g-consecutive: coalesced
    #pragma unroll
    for (int p = 0; p < 8; p++) {
        float a, b; unpack2(acc[p], a, b);
        outp[(size_t)(2*p    ) * G_] = a;
        outp[(size_t)(2*p + 1) * G_] = b;
    }
}

// ====================== kernel 2: recurrence ================================
__global__ void __launch_bounds__(512, 1)
lstm_rec(const float* __restrict__ W_hh,
         const float* __restrict__ W_out,
         const float* __restrict__ b_out,
         float* __restrict__ out)
{
    __shared__ __align__(16) float hsT4[H_][4];        // [unit][row], 16B/unit
    __shared__ __align__(16) float pq[8][4][4][H_];    // [ks][class][row][u] 32KB
    __shared__ __align__(16) u64   pc[8][2][OUT_];     // [kc][rowpair][o] 6KB

    const int tid  = threadIdx.x;
    const int row0 = blockIdx.x * ROWS;

    // ---- Phase A identity: (unit ua, k-eighth ks); gates = ua + 64c ----
    const int ua = tid & 63;
    const int ks = tid >> 6;                 // 0..7, k in [8ks, 8ks+8)
    u64 wA[4][8];                            // dup (w,w), 64 regs
    #pragma unroll
    for (int c = 0; c < 4; c++)
        #pragma unroll
        for (int j = 0; j < 8; j++) {
            float v = W_hh[(c*64 + ua)*H_ + ks*8 + j];
            wA[c][j] = pack2(v, v);
        }
    const u64 zero2 = pack2(0.0f, 0.0f);

    // ---- Phase B identity (tid<256): (unit ub, row rb) ----
    const int ub = tid & 63;
    const int rb = (tid >> 6) & 3;
    float cst = 0.0f;
    const size_t xgbase = ((size_t)(row0 + rb) * T_) * G_ + ub;
    float xg0 = 0, xg1 = 0, xg2 = 0, xg3 = 0;
    if (tid < 256) {
        xg0 = g_xg[xgbase      ];
        xg1 = g_xg[xgbase +  64];
        xg2 = g_xg[xgbase + 128];
        xg3 = g_xg[xgbase + 192];
    }

    // ---- head C1 identity (tid<384): (output co, k-eighth kc) ----
    const int co = tid % 48;
    const int kc = tid / 48;                 // 0..7 valid when tid<384
    u64 wo[8];
    u64 cb2 = zero2;
    if (tid < 384) {
        #pragma unroll
        for (int j = 0; j < 8; j++) {
            float v = W_out[co*H_ + kc*8 + j];
            wo[j] = pack2(v, v);
        }
        if (kc == 0) { float b = b_out[co]; cb2 = pack2(b, b); }
    }
    // ---- head C2 identity (tid in [384,480)): (output co2, rowpair rp2) ----
    const int i2  = tid - 384;               // valid when 0 <= i2 < 96
    const int co2 = (i2 >= 0) ? (i2 % 48) : 0;
    const int rp2 = (i2 >= 0) ? (i2 / 48) : 0;

    if (tid < H_) {
        hsT4[tid][0] = 0.0f; hsT4[tid][1] = 0.0f;
        hsT4[tid][2] = 0.0f; hsT4[tid][3] = 0.0f;
    }
    __syncthreads();

    for (int t = 0; t < T_; t++) {
        // ---- Phase A: 8 broadcast LDS.128 -> 64 FFMA2 (all 512 threads) ----
        {
            u64 a01[4] = {zero2, zero2, zero2, zero2};
            u64 a23[4] = {zero2, zero2, zero2, zero2};
            const ulonglong2* hp = (const ulonglong2*)hsT4 + ks*8;
            #pragma unroll
            for (int j = 0; j < 8; j++) {
                ulonglong2 q = hp[j];        // .x=(r0,r1) .y=(r2,r3)
                #pragma unroll
                for (int c = 0; c < 4; c++) {
                    a01[c] = fma2(wA[c][j], q.x, a01[c]);
                    a23[c] = fma2(wA[c][j], q.y, a23[c]);
                }
            }
            #pragma unroll
            for (int c = 0; c < 4; c++) {
                float v0, v1;
                unpack2(a01[c], v0, v1);
                pq[ks][c][0][ua] = v0; pq[ks][c][1][ua] = v1;
                unpack2(a23[c], v0, v1);
                pq[ks][c][2][ua] = v0; pq[ks][c][3][ua] = v1;
            }
        }
        __syncthreads();   // bar1

        if (tid < 256) {
            // ---- Phase B: sum 8 partials + xg, activations, state update ----
            float si = xg0 + (((pq[0][0][rb][ub] + pq[1][0][rb][ub])
                             + (pq[2][0][rb][ub] + pq[3][0][rb][ub]))
                            + ((pq[4][0][rb][ub] + pq[5][0][rb][ub])
                             + (pq[6][0][rb][ub] + pq[7][0][rb][ub])));
            float sf = xg1 + (((pq[0][1][rb][ub] + pq[1][1][rb][ub])
                             + (pq[2][1][rb][ub] + pq[3][1][rb][ub]))
                            + ((pq[4][1][rb][ub] + pq[5][1][rb][ub])
                             + (pq[6][1][rb][ub] + pq[7][1][rb][ub])));
            float sg = xg2 + (((pq[0][2][rb][ub] + pq[1][2][rb][ub])
                             + (pq[2][2][rb][ub] + pq[3][2][rb][ub]))
                            + ((pq[4][2][rb][ub] + pq[5][2][rb][ub])
                             + (pq[6][2][rb][ub] + pq[7][2][rb][ub])));
            float so = xg3 + (((pq[0][3][rb][ub] + pq[1][3][rb][ub])
                             + (pq[2][3][rb][ub] + pq[3][3][rb][ub]))
                            + ((pq[4][3][rb][ub] + pq[5][3][rb][ub])
                             + (pq[6][3][rb][ub] + pq[7][3][rb][ub])));
            float iv = sigm(si), fv = sigm(sf);
            float gv = tanh_(sg), ov = sigm(so);
            cst = fv * cst + iv * gv;
            hsT4[ub][rb] = ov * tanh_(cst);

            if (t + 1 < T_) {                // prefetch next xg
                const size_t o = xgbase + (size_t)(t + 1) * G_;
                xg0 = g_xg[o      ]; xg1 = g_xg[o +  64];
                xg2 = g_xg[o + 128]; xg3 = g_xg[o + 192];
            }
        } else if (i2 >= 0 && i2 < 96 && t > 0) {
            // ---- head C2: reduce step t-1 partials, emit y ----
            u64 s = add2(add2(add2(pc[0][rp2][co2], pc[1][rp2][co2]),
                              add2(pc[2][rp2][co2], pc[3][rp2][co2])),
                         add2(add2(pc[4][rp2][co2], pc[5][rp2][co2]),
                              add2(pc[6][rp2][co2], pc[7][rp2][co2])));
            float z0, z1; unpack2(s, z0, z1);
            out[((size_t)(row0 + 2*rp2    ) * T_ + (t-1)) * OUT_ + co2] = sigm(z0);
            out[((size_t)(row0 + 2*rp2 + 1) * T_ + (t-1)) * OUT_ + co2] = sigm(z1);
        }
        __syncthreads();   // bar2

        // ---- head C1: out-head partials for step t (fresh h) ----
        if (tid < 384) {
            u64 a01 = cb2, a23 = cb2;
            const ulonglong2* hp = (const ulonglong2*)hsT4 + kc*8;
            #pragma unroll
            for (int j = 0; j < 8; j++) {
                ulonglong2 q = hp[j];
                a01 = fma2(wo[j], q.x, a01);
                a23 = fma2(wo[j], q.y, a23);
            }
            pc[kc][0][co] = a01;
            pc[kc][1][co] = a23;
        }
        // no bar: next A only reads hsT (as does C1); A(t+1)'s pq writes are
        // safe (B(t) readers passed bar2); pc written here is read by C2 only
        // after the next bar1.
    }

    // ---- epilogue: emit t = T-1 ----
    __syncthreads();
    if (i2 >= 0 && i2 < 96) {
        u64 s = add2(add2(add2(pc[0][rp2][co2], pc[1][rp2][co2]),
                          add2(pc[2][rp2][co2], pc[3][rp2][co2])),
                     add2(add2(pc[4][rp2][co2], pc[5][rp2][co2]),
                          add2(pc[6][rp2][co2], pc[7][rp2][co2])));
        float z0, z1; unpack2(s, z0, z1);
        out[((size_t)(row0 + 2*rp2    ) * T_ + (T_-1)) * OUT_ + co2] = sigm(z0);
        out[((size_t)(row0 + 2*rp2 + 1) * T_ + (T_-1)) * OUT_ + co2] = sigm(z1);
    }
}

extern "C" void kernel_launch(void* const* d_in, const int* in_sizes, int n_in,
                              void* d_out, int out_size)
{
    (void)in_sizes; (void)n_in; (void)out_size;
    const float* x     = (const float*)d_in[0];
    const float* W_ih  = (const float*)d_in[1];
    const float* W_hh  = (const float*)d_in[2];
    const float* b_ih  = (const float*)d_in[3];
    const float* b_hh  = (const float*)d_in[4];
    const float* W_out = (const float*)d_in[5];
    const float* b_out = (const float*)d_in[6];
    float* out = (float*)d_out;

    xproj_T<<<(B_*T_)/XTILE, 512>>>(x, W_ih, b_ih, b_hh);
    lstm_rec<<<CTAS, 512>>>(W_hh, W_out, b_out, out);
}

// round 10
// speedup vs baseline: 1.0273x; 1.0273x over previous
#include <cuda_runtime.h>

// LSTM: B=512, T=1000, IN=39, H=64 (4H=256 gates), OUT=48.
// R10:
//  - rec: R7 geometry (256 thr, k-split 4) but Phase A stores partials as
//    8 STS.64 (u64 accumulators direct, pq01/pq23 split) instead of 16
//    STS.32 -> halves STS in flight at bar1. Theory: BAR drains pending STS
//    at ~36·n_STS (B300 doc); R7=R9 at ~970us despite 2x occupancy points
//    at this fixed per-step drain, not issue capacity.
//  - xproj: 256 thr, 16-row tile, __launch_bounds__(256,2) (~101 regs, 2
//    CTAs/SM), coalesced LDG staging (tile is contiguous), 20-float padded
//    T-layout (aligned LDS.128, <=4-way STS conflicts). R9's 512-thr
//    version spilled at the 128 cap (~718us); floor is 172us.

#define B_    512
#define T_    1000
#define IN_   39
#define H_    64
#define G_    256
#define OUT_  48
#define ROWS  4
#define CTAS  (B_/ROWS)   // 128
#define XT    16          // xproj bt-tile

typedef unsigned long long u64;

__device__ float g_xg[(size_t)B_ * T_ * G_];   // 512 MB x-projection scratch

__device__ __forceinline__ u64 fma2(u64 a, u64 b, u64 c) {
    u64 d;
    asm("fma.rn.f32x2 %0, %1, %2, %3;" : "=l"(d) : "l"(a), "l"(b), "l"(c));
    return d;
}
__device__ __forceinline__ u64 add2(u64 a, u64 b) {
    u64 d;
    asm("add.rn.f32x2 %0, %1, %2;" : "=l"(d) : "l"(a), "l"(b));
    return d;
}
__device__ __forceinline__ u64 pack2(float lo, float hi) {
    u64 d;
    asm("mov.b64 %0, {%1, %2};" : "=l"(d) : "f"(lo), "f"(hi));
    return d;
}
__device__ __forceinline__ void unpack2(u64 v, float &lo, float &hi) {
    asm("mov.b64 {%0, %1}, %2;" : "=f"(lo), "=f"(hi) : "l"(v));
}
__device__ __forceinline__ float sigm(float x) {
    return __fdividef(1.0f, 1.0f + __expf(-x));
}
__device__ __forceinline__ float tanh_(float x) {
    float e = __expf(2.0f * x);
    return 1.0f - __fdividef(2.0f, e + 1.0f);
}

// ====================== kernel 1: x projection ==============================
// 256 threads (thread = gate), 16-bt tile, 2 CTAs/SM.
__global__ void __launch_bounds__(256, 2)
xproj_T(const float* __restrict__ x,
        const float* __restrict__ W_ih,
        const float* __restrict__ b_ih,
        const float* __restrict__ b_hh)
{
    __shared__ __align__(16) float xT[IN_][XT + 4];  // pad 16->20: aligned rows
    const int g = threadIdx.x;
    const size_t bt0 = (size_t)blockIdx.x * XT;

    u64 w[IN_];
    #pragma unroll
    for (int k = 0; k < IN_; k++) {
        float v = W_ih[g*IN_ + k];
        w[k] = pack2(v, v);
    }
    const float bias = b_ih[g] + b_hh[g];
    const u64 bias2 = pack2(bias, bias);

    // stage: tile is a contiguous region of x -> coalesced scalar LDG
    {
        const float* src = x + bt0 * IN_;
        for (int idx = threadIdx.x; idx < XT*IN_; idx += 256) {
            int r = idx / IN_, i = idx - r*IN_;
            xT[i][r] = src[idx];
        }
    }
    __syncthreads();

    u64 acc[XT/2];
    #pragma unroll
    for (int p = 0; p < XT/2; p++) acc[p] = bias2;

    #pragma unroll
    for (int k = 0; k < IN_; k++) {
        const ulonglong2* xp = (const ulonglong2*)xT[k];   // 80B rows: aligned
        const u64 wk = w[k];
        #pragma unroll
        for (int q = 0; q < XT/4; q++) {
            ulonglong2 v = xp[q];
            acc[2*q    ] = fma2(wk, v.x, acc[2*q    ]);
            acc[2*q + 1] = fma2(wk, v.y, acc[2*q + 1]);
        }
    }

    float* outp = g_xg + bt0 * G_ + g;     // g-consecutive -> coalesced
    #pragma unroll
    for (int p = 0; p < XT/2; p++) {
        float a, b; unpack2(acc[p], a, b);
        outp[(size_t)(2*p    ) * G_] = a;
        outp[(size_t)(2*p + 1) * G_] = b;
    }
}

// ====================== kernel 2: recurrence ================================
__global__ void __launch_bounds__(256, 1)
lstm_rec(const float* __restrict__ W_hh,
         const float* __restrict__ W_out,
         const float* __restrict__ b_out,
         float* __restrict__ out)
{
    __shared__ __align__(16) float hsT4[H_][4];     // [unit][row] = ulonglong2
    __shared__ __align__(16) u64 pq01[4][4][H_];    // [ks][class][gate-unit] (r0,r1) 8KB
    __shared__ __align__(16) u64 pq23[4][4][H_];    // same for (r2,r3)             8KB
    __shared__ __align__(16) u64 pc01[4][OUT_];     // head partials (r0,r1) 1.5KB
    __shared__ __align__(16) u64 pc23[4][OUT_];     // head partials (r2,r3) 1.5KB

    const int tid  = threadIdx.x;
    const int row0 = blockIdx.x * ROWS;

    // ---- Phase A identity: (gate-unit ua, k-quarter ks); gates = ua + 64c ----
    const int ua = tid & 63;
    const int ks = tid >> 6;                 // 0..3, k in [16ks,16ks+16)
    u64 wA[4][16];                           // dup (w,w), 128 regs
    #pragma unroll
    for (int c = 0; c < 4; c++)
        #pragma unroll
        for (int j = 0; j < 16; j++) {
            float v = W_hh[(c*64 + ua)*H_ + ks*16 + j];
            wA[c][j] = pack2(v, v);
        }
    const u64 zero2 = pack2(0.0f, 0.0f);

    // ---- Phase B identity (all 256): (unit ub, row rb) ----
    const int ub = tid & 63;
    const int rb = tid >> 6;
    const int rhalf = rb >> 1;               // 0: rows 0,1 -> pq01; 1: pq23
    const int rlane = rb & 1;
    float cst = 0.0f;
    const size_t xgbase = ((size_t)(row0 + rb) * T_) * G_ + ub;
    float xg0 = g_xg[xgbase      ];
    float xg1 = g_xg[xgbase +  64];
    float xg2 = g_xg[xgbase + 128];
    float xg3 = g_xg[xgbase + 192];

    // ---- head C1 identity (tid<192): (output co, k-quarter kc) ----
    const int co = tid % 48;
    const int kc = tid / 48;                 // 0..3 valid when tid<192
    u64 wo[16];
    u64 cb2 = zero2;
    if (tid < 192) {
        #pragma unroll
        for (int j = 0; j < 16; j++) {
            float v = W_out[co*H_ + kc*16 + j];
            wo[j] = pack2(v, v);
        }
        if (kc == 0) { float b = b_out[co]; cb2 = pack2(b, b); }
    }
    // ---- head C2 identity (tid<96): (output co2, rowpair rp2) ----
    const int co2 = tid % 48;
    const int rp2 = tid / 48;                // 0..1 valid when tid<96

    if (tid < H_) {
        hsT4[tid][0] = 0.0f; hsT4[tid][1] = 0.0f;
        hsT4[tid][2] = 0.0f; hsT4[tid][3] = 0.0f;
    }
    __syncthreads();

    for (int t = 0; t < T_; t++) {
        // ---- Phase A: 16 broadcast LDS.128 -> 128 FFMA2, 8 STS.64 ----
        {
            u64 a01[4] = {zero2, zero2, zero2, zero2};
            u64 a23[4] = {zero2, zero2, zero2, zero2};
            const ulonglong2* hp = (const ulonglong2*)hsT4 + ks*16;
            #pragma unroll
            for (int j = 0; j < 16; j++) {
                ulonglong2 q = hp[j];        // .x=(r0,r1) .y=(r2,r3)
                #pragma unroll
                for (int c = 0; c < 4; c++) {
                    a01[c] = fma2(wA[c][j], q.x, a01[c]);
                    a23[c] = fma2(wA[c][j], q.y, a23[c]);
                }
            }
            #pragma unroll
            for (int c = 0; c < 4; c++) {
                pq01[ks][c][ua] = a01[c];
                pq23[ks][c][ua] = a23[c];
            }
        }
        __syncthreads();   // bar1 (8 STS.64 in flight, was 16 STS.32)

        // ---- head C2: reduce step t-1 partials, emit y (tid<96) ----
        if (tid < 96 && t > 0) {
            const u64* pcx = rp2 ? pc23[0] : pc01[0];
            u64 s = add2(add2(pcx[0*OUT_ + co2], pcx[1*OUT_ + co2]),
                         add2(pcx[2*OUT_ + co2], pcx[3*OUT_ + co2]));
            float z0, z1; unpack2(s, z0, z1);
            out[((size_t)(row0 + 2*rp2    ) * T_ + (t-1)) * OUT_ + co2] = sigm(z0);
            out[((size_t)(row0 + 2*rp2 + 1) * T_ + (t-1)) * OUT_ + co2] = sigm(z1);
        }

        // ---- Phase B: sum partials + xg, activations, state update ----
        {
            const float* pqf = (const float*)(rhalf ? pq23 : pq01) + rlane;
            #define PQ(ksx, cx) pqf[(((ksx)*4 + (cx))*H_ + ub)*2]
            float si = xg0 + ((PQ(0,0) + PQ(1,0)) + (PQ(2,0) + PQ(3,0)));
            float sf = xg1 + ((PQ(0,1) + PQ(1,1)) + (PQ(2,1) + PQ(3,1)));
            float sg = xg2 + ((PQ(0,2) + PQ(1,2)) + (PQ(2,2) + PQ(3,2)));
            float so = xg3 + ((PQ(0,3) + PQ(1,3)) + (PQ(2,3) + PQ(3,3)));
            #undef PQ
            float iv = sigm(si), fv = sigm(sf);
            float gv = tanh_(sg), ov = sigm(so);
            cst = fv * cst + iv * gv;
            hsT4[ub][rb] = ov * tanh_(cst);

            if (t + 1 < T_) {                // prefetch next xg
                const size_t o = xgbase + (size_t)(t + 1) * G_;
                xg0 = g_xg[o      ]; xg1 = g_xg[o +  64];
                xg2 = g_xg[o + 128]; xg3 = g_xg[o + 192];
            }
        }
        __syncthreads();   // bar2 (1 STS.32 in flight)

        // ---- head C1: out-head partials for step t (fresh h) ----
        if (tid < 192) {
            u64 a01 = cb2, a23 = cb2;
            const ulonglong2* hp = (const ulonglong2*)hsT4 + kc*16;
            #pragma unroll
            for (int j = 0; j < 16; j++) {
                ulonglong2 q = hp[j];
                a01 = fma2(wo[j], q.x, a01);
                a23 = fma2(wo[j], q.y, a23);
            }
            pc01[kc][co] = a01;    // far from any barrier: drains for free
            pc23[kc][co] = a23;
        }
        // no bar: next A only reads hsT4 (C1 also reads); A(t+1)'s pq writes
        // are safe (B(t) readers passed bar2); pc written here is read by C2
        // only after the next bar1.
    }

    // ---- epilogue: emit t = T-1 ----
    __syncthreads();
    if (tid < 96) {
        const u64* pcx = rp2 ? pc23[0] : pc01[0];
        u64 s = add2(add2(pcx[0*OUT_ + co2], pcx[1*OUT_ + co2]),
                     add2(pcx[2*OUT_ + co2], pcx[3*OUT_ + co2]));
        float z0, z1; unpack2(s, z0, z1);
        out[((size_t)(row0 + 2*rp2    ) * T_ + (T_-1)) * OUT_ + co2] = sigm(z0);
        out[((size_t)(row0 + 2*rp2 + 1) * T_ + (T_-1)) * OUT_ + co2] = sigm(z1);
    }
}

extern "C" void kernel_launch(void* const* d_in, const int* in_sizes, int n_in,
                              void* d_out, int out_size)
{
    (void)in_sizes; (void)n_in; (void)out_size;
    const float* x     = (const float*)d_in[0];
    const float* W_ih  = (const float*)d_in[1];
    const float* W_hh  = (const float*)d_in[2];
    const float* b_ih  = (const float*)d_in[3];
    const float* b_hh  = (const float*)d_in[4];
    const float* W_out = (const float*)d_in[5];
    const float* b_out = (const float*)d_in[6];
    float* out = (float*)d_out;

    xproj_T<<<(B_*T_)/XT, 256>>>(x, W_ih, b_ih, b_hh);
    lstm_rec<<<CTAS, 256>>>(W_hh, W_out, b_out, out);
}

// round 11
// speedup vs baseline: 1.3173x; 1.2823x over previous
#include <cuda_runtime.h>

// LSTM: B=512, T=1000, IN=39, H=64 (4H=256 gates), OUT=48.
// R11: SINGLE fused persistent kernel (xproj kernel + 512MB scratch deleted).
// Phase A computes W_ih·x(t) + W_hh·h(t-1) + b directly into the pq
// partials: h-part via R7's dup-weight/rowpair-packed scheme (16 LDS.128 ->
// 128 FFMA2), x-part via pair-packed non-dup weights (12 LDS.128 -> 96
// FFMA2, per-row transient accumulators to cap regs ~230). x staged into a
// double-buffered SMEM tile by 156 stager threads (LDG at loop top, STS in
// B -> one full phase of latency cover). W_out lives in SMEM (dup u64) to
// free the registers the x-weights need. Rationale: R7-R10 showed rec's
// ~1250cyc/step overhead is insensitive to occupancy/STS-shape; only total
// work moves dur, and xproj was ~465-620us of pure extra work.

#define B_    512
#define T_    1000
#define IN_   39
#define H_    64
#define G_    256
#define OUT_  48
#define ROWS  4
#define CTAS  (B_/ROWS)   // 128
#define KXP   48          // x scalars padded 39->48 (24 pairs, 6 pairs/quarter)

typedef unsigned long long u64;

__device__ __forceinline__ u64 fma2(u64 a, u64 b, u64 c) {
    u64 d;
    asm("fma.rn.f32x2 %0, %1, %2, %3;" : "=l"(d) : "l"(a), "l"(b), "l"(c));
    return d;
}
__device__ __forceinline__ u64 add2(u64 a, u64 b) {
    u64 d;
    asm("add.rn.f32x2 %0, %1, %2;" : "=l"(d) : "l"(a), "l"(b));
    return d;
}
__device__ __forceinline__ u64 pack2(float lo, float hi) {
    u64 d;
    asm("mov.b64 %0, {%1, %2};" : "=l"(d) : "f"(lo), "f"(hi));
    return d;
}
__device__ __forceinline__ void unpack2(u64 v, float &lo, float &hi) {
    asm("mov.b64 {%0, %1}, %2;" : "=f"(lo), "=f"(hi) : "l"(v));
}
__device__ __forceinline__ float sigm(float x) {
    return __fdividef(1.0f, 1.0f + __expf(-x));
}
__device__ __forceinline__ float tanh_(float x) {
    float e = __expf(2.0f * x);
    return 1.0f - __fdividef(2.0f, e + 1.0f);
}

__global__ void __launch_bounds__(256, 1)
lstm_fused(const float* __restrict__ x,
           const float* __restrict__ W_ih,
           const float* __restrict__ W_hh,
           const float* __restrict__ b_ih,
           const float* __restrict__ b_hh,
           const float* __restrict__ W_out,
           const float* __restrict__ b_out,
           float* __restrict__ out)
{
    __shared__ __align__(16) float hsT4[H_][4];      // [unit][row] rowpack, 1KB
    __shared__ __align__(16) float pq[4][4][4][H_];  // [ks][class][row][u] 16KB
    __shared__ __align__(16) u64   pc[4][2][OUT_];   // head partials 3KB
    __shared__ __align__(16) u64   woS[H_][OUT_];    // dup W_out 24KB
    __shared__ __align__(16) float xs[2][ROWS][KXP]; // x tile dbl-buf 1.5KB

    const int tid  = threadIdx.x;
    const int row0 = blockIdx.x * ROWS;

    // ---- Phase A identity: (unit ua, k-quarter ks); gates = ua + 64c ----
    const int ua = tid & 63;
    const int ks = tid >> 6;                 // 0..3
    u64 wA[4][16];                           // h-part dup (w,w): 128 regs
    #pragma unroll
    for (int c = 0; c < 4; c++)
        #pragma unroll
        for (int j = 0; j < 16; j++) {
            float v = W_hh[(c*64 + ua)*H_ + ks*16 + j];
            wA[c][j] = pack2(v, v);
        }
    u64 wx[4][6];                            // x-part pair weights: 48 regs
    #pragma unroll
    for (int c = 0; c < 4; c++)
        #pragma unroll
        for (int j = 0; j < 6; j++) {
            int k0 = (ks*6 + j)*2, k1 = k0 + 1;
            float lo = (k0 < IN_) ? W_ih[(c*64 + ua)*IN_ + k0] : 0.0f;
            float hi = (k1 < IN_) ? W_ih[(c*64 + ua)*IN_ + k1] : 0.0f;
            wx[c][j] = pack2(lo, hi);
        }
    const u64 zero2 = pack2(0.0f, 0.0f);
    u64 bias2c[4];                           // (b,0): ks==0 threads only
    #pragma unroll
    for (int c = 0; c < 4; c++) {
        float b = (ks == 0) ? (b_ih[c*64 + ua] + b_hh[c*64 + ua]) : 0.0f;
        bias2c[c] = pack2(b, 0.0f);
    }

    // ---- Phase B identity: (unit ub, row rb) ----
    const int ub = tid & 63;
    const int rb = tid >> 6;
    float cst = 0.0f;

    // ---- stager identity (tid<156): x element (sr, si) ----
    const bool stg = (tid < ROWS*IN_);
    const int  sr  = stg ? (tid / IN_) : 0;
    const int  si  = stg ? (tid % IN_) : 0;

    // ---- head C1 identity (tid<192): (output co, k-quarter kc) ----
    const int co = tid % 48;
    const int kc = tid / 48;
    u64 cb2 = zero2;
    if (tid < 192 && kc == 0) { float b = b_out[co]; cb2 = pack2(b, b); }
    // ---- head C2 identity (tid<96): (output co2, rowpair rp2) ----
    const int co2 = tid % 48;
    const int rp2 = tid / 48;

    // ---- prologue: zero buffers, stage W_out + x(0) ----
    for (int idx = tid; idx < 2*ROWS*KXP; idx += 256)
        ((float*)xs)[idx] = 0.0f;
    if (tid < H_) {
        hsT4[tid][0] = 0.0f; hsT4[tid][1] = 0.0f;
        hsT4[tid][2] = 0.0f; hsT4[tid][3] = 0.0f;
    }
    __syncthreads();
    for (int idx = tid; idx < H_*OUT_; idx += 256) {
        int k = idx / OUT_, o = idx % OUT_;
        float v = W_out[o*H_ + k];
        woS[k][o] = pack2(v, v);
    }
    if (stg) xs[0][sr][si] = x[((size_t)(row0 + sr) * T_) * IN_ + si];
    __syncthreads();

    float xnext = 0.0f;
    for (int t = 0; t < T_; t++) {
        const int p = t & 1;
        const bool pf = stg && (t + 1 < T_);
        if (pf) xnext = x[((size_t)(row0 + sr) * T_ + (t + 1)) * IN_ + si];

        // ---- Phase A: h-part (16 LDS.128 -> 128 FFMA2) then x-part
        //      (12 LDS.128 -> 96 FFMA2), folded into pq ----
        {
            u64 a01[4] = {zero2, zero2, zero2, zero2};
            u64 a23[4] = {zero2, zero2, zero2, zero2};
            const ulonglong2* hp = (const ulonglong2*)hsT4 + ks*16;
            #pragma unroll
            for (int j = 0; j < 16; j++) {
                ulonglong2 q = hp[j];        // .x=(r0,r1) .y=(r2,r3)
                #pragma unroll
                for (int c = 0; c < 4; c++) {
                    a01[c] = fma2(wA[c][j], q.x, a01[c]);
                    a23[c] = fma2(wA[c][j], q.y, a23[c]);
                }
            }
            // unpack h-part to 16 floats to cap register pressure
            float hv[4][4];
            #pragma unroll
            for (int c = 0; c < 4; c++) {
                unpack2(a01[c], hv[c][0], hv[c][1]);
                unpack2(a23[c], hv[c][2], hv[c][3]);
            }
            // x-part per row: transient 4 accumulators
            #pragma unroll
            for (int r = 0; r < 4; r++) {
                u64 axr[4];
                #pragma unroll
                for (int c = 0; c < 4; c++) axr[c] = bias2c[c];
                const ulonglong2* xp = (const ulonglong2*)xs[p][r] + ks*3;
                #pragma unroll
                for (int m = 0; m < 3; m++) {
                    ulonglong2 q = xp[m];    // pairs (4 scalars) of row r
                    #pragma unroll
                    for (int c = 0; c < 4; c++) {
                        axr[c] = fma2(wx[c][2*m    ], q.x, axr[c]);
                        axr[c] = fma2(wx[c][2*m + 1], q.y, axr[c]);
                    }
                }
                #pragma unroll
                for (int c = 0; c < 4; c++) {
                    float e, f; unpack2(axr[c], e, f);
                    pq[ks][c][r][ua] = hv[c][r] + (e + f);
                }
            }
        }
        __syncthreads();   // bar1

        // ---- head C2: reduce step t-1 partials, emit y (tid<96) ----
        if (tid < 96 && t > 0) {
            u64 s = add2(add2(pc[0][rp2][co2], pc[1][rp2][co2]),
                         add2(pc[2][rp2][co2], pc[3][rp2][co2]));
            float z0, z1; unpack2(s, z0, z1);
            out[((size_t)(row0 + 2*rp2    ) * T_ + (t-1)) * OUT_ + co2] = sigm(z0);
            out[((size_t)(row0 + 2*rp2 + 1) * T_ + (t-1)) * OUT_ + co2] = sigm(z1);
        }

        // ---- Phase B: sum partials, activations, state update (all 256) ----
        {
            float si_ = (pq[0][0][rb][ub] + pq[1][0][rb][ub])
                      + (pq[2][0][rb][ub] + pq[3][0][rb][ub]);
            float sf_ = (pq[0][1][rb][ub] + pq[1][1][rb][ub])
                      + (pq[2][1][rb][ub] + pq[3][1][rb][ub]);
            float sg_ = (pq[0][2][rb][ub] + pq[1][2][rb][ub])
                      + (pq[2][2][rb][ub] + pq[3][2][rb][ub]);
            float so_ = (pq[0][3][rb][ub] + pq[1][3][rb][ub])
                      + (pq[2][3][rb][ub] + pq[3][3][rb][ub]);
            float iv = sigm(si_), fv = sigm(sf_);
            float gv = tanh_(sg_), ov = sigm(so_);
            cst = fv * cst + iv * gv;
            hsT4[ub][rb] = ov * tanh_(cst);
        }
        if (pf) xs[p ^ 1][sr][si] = xnext;   // publish x(t+1)
        __syncthreads();   // bar2

        // ---- head C1: out-head partials for step t (fresh h, wo from SMEM) ----
        if (tid < 192) {
            u64 a01 = cb2, a23 = cb2;
            const ulonglong2* hp = (const ulonglong2*)hsT4 + kc*16;
            #pragma unroll
            for (int j = 0; j < 16; j++) {
                ulonglong2 q = hp[j];
                u64 w = woS[kc*16 + j][co];
                a01 = fma2(w, q.x, a01);
                a23 = fma2(w, q.y, a23);
            }
            pc[kc][0][co] = a01;
            pc[kc][1][co] = a23;
        }
        // no bar: next A reads hsT4 (C1 also reads) and xs (published before
        // bar2); pq writes of A(t+1) are safe (B(t) readers passed bar2);
        // pc written here is read by C2 only after the next bar1.
    }

    // ---- epilogue: emit t = T-1 ----
    __syncthreads();
    if (tid < 96) {
        u64 s = add2(add2(pc[0][rp2][co2], pc[1][rp2][co2]),
                     add2(pc[2][rp2][co2], pc[3][rp2][co2]));
        float z0, z1; unpack2(s, z0, z1);
        out[((size_t)(row0 + 2*rp2    ) * T_ + (T_-1)) * OUT_ + co2] = sigm(z0);
        out[((size_t)(row0 + 2*rp2 + 1) * T_ + (T_-1)) * OUT_ + co2] = sigm(z1);
    }
}

extern "C" void kernel_launch(void* const* d_in, const int* in_sizes, int n_in,
                              void* d_out, int out_size)
{
    (void)in_sizes; (void)n_in; (void)out_size;
    const float* x     = (const float*)d_in[0];
    const float* W_ih  = (const float*)d_in[1];
    const float* W_hh  = (const float*)d_in[2];
    const float* b_ih  = (const float*)d_in[3];
    const float* b_hh  = (const float*)d_in[4];
    const float* W_out = (const float*)d_in[5];
    const float* b_out = (const float*)d_in[6];
    float* out = (float*)d_out;

    lstm_fused<<<CTAS, 256>>>(x, W_ih, W_hh, b_ih, b_hh, W_out, b_out, out);
}

// round 12
// speedup vs baseline: 1.5591x; 1.1836x over previous
#include <cuda_runtime.h>

// LSTM: B=512, T=1000, IN=39, H=64 (4H=256 gates), OUT=48.
// R12 = R11 + head pipelined INTO the B-window (post-bar2 phase deleted):
//  - hsT4 double-buffered: B(t) writes buf t&1 while C1 computes the output
//    head of h(t-1) from buf (t+1)&1 in the SAME window, filling the idle
//    FMA slots under B's serial MUFU chains.
//  - pc double-buffered: C2 emits y(t-2) from the other buffer, also in the
//    B-window (threads 0-47; C1 on 64-255; B on all).
//  - W_out stored un-dup'd (float, 12KB) to fit static smem with the new
//    double buffers (~37.5KB).
// Per-step serial path becomes A(FMA floor ~896cyc) + bar1 + max(B-serial,
// C1-issue) + bar2 — C1's ~150cyc serial tail after bar2 is gone.

#define B_    512
#define T_    1000
#define IN_   39
#define H_    64
#define G_    256
#define OUT_  48
#define ROWS  4
#define CTAS  (B_/ROWS)   // 128
#define KXP   48          // x scalars padded 39->48 (24 pairs, 6 pairs/quarter)

typedef unsigned long long u64;

__device__ __forceinline__ u64 fma2(u64 a, u64 b, u64 c) {
    u64 d;
    asm("fma.rn.f32x2 %0, %1, %2, %3;" : "=l"(d) : "l"(a), "l"(b), "l"(c));
    return d;
}
__device__ __forceinline__ u64 add2(u64 a, u64 b) {
    u64 d;
    asm("add.rn.f32x2 %0, %1, %2;" : "=l"(d) : "l"(a), "l"(b));
    return d;
}
__device__ __forceinline__ u64 pack2(float lo, float hi) {
    u64 d;
    asm("mov.b64 %0, {%1, %2};" : "=l"(d) : "f"(lo), "f"(hi));
    return d;
}
__device__ __forceinline__ void unpack2(u64 v, float &lo, float &hi) {
    asm("mov.b64 {%0, %1}, %2;" : "=f"(lo), "=f"(hi) : "l"(v));
}
__device__ __forceinline__ float sigm(float x) {
    return __fdividef(1.0f, 1.0f + __expf(-x));
}
__device__ __forceinline__ float tanh_(float x) {
    float e = __expf(2.0f * x);
    return 1.0f - __fdividef(2.0f, e + 1.0f);
}

__global__ void __launch_bounds__(256, 1)
lstm_fused(const float* __restrict__ x,
           const float* __restrict__ W_ih,
           const float* __restrict__ W_hh,
           const float* __restrict__ b_ih,
           const float* __restrict__ b_hh,
           const float* __restrict__ W_out,
           const float* __restrict__ b_out,
           float* __restrict__ out)
{
    __shared__ __align__(16) float hsT4[2][H_][4];   // dbl-buf rowpack h, 2KB
    __shared__ __align__(16) float pq[4][4][4][H_];  // [ks][class][row][u] 16KB
    __shared__ __align__(16) u64   pc[2][4][2][OUT_];// dbl-buf head partials 6KB
    __shared__ __align__(16) float woS[H_][OUT_];    // W_out un-dup'd 12KB
    __shared__ __align__(16) float xs[2][ROWS][KXP]; // x tile dbl-buf 1.5KB

    const int tid  = threadIdx.x;
    const int row0 = blockIdx.x * ROWS;

    // ---- Phase A identity: (unit ua, k-quarter ks); gates = ua + 64c ----
    const int ua = tid & 63;
    const int ks = tid >> 6;                 // 0..3
    u64 wA[4][16];                           // h-part dup (w,w): 128 regs
    #pragma unroll
    for (int c = 0; c < 4; c++)
        #pragma unroll
        for (int j = 0; j < 16; j++) {
            float v = W_hh[(c*64 + ua)*H_ + ks*16 + j];
            wA[c][j] = pack2(v, v);
        }
    u64 wx[4][6];                            // x-part pair weights: 48 regs
    #pragma unroll
    for (int c = 0; c < 4; c++)
        #pragma unroll
        for (int j = 0; j < 6; j++) {
            int k0 = (ks*6 + j)*2, k1 = k0 + 1;
            float lo = (k0 < IN_) ? W_ih[(c*64 + ua)*IN_ + k0] : 0.0f;
            float hi = (k1 < IN_) ? W_ih[(c*64 + ua)*IN_ + k1] : 0.0f;
            wx[c][j] = pack2(lo, hi);
        }
    const u64 zero2 = pack2(0.0f, 0.0f);
    u64 bias2c[4];                           // (b,0): ks==0 threads only
    #pragma unroll
    for (int c = 0; c < 4; c++) {
        float b = (ks == 0) ? (b_ih[c*64 + ua] + b_hh[c*64 + ua]) : 0.0f;
        bias2c[c] = pack2(b, 0.0f);
    }

    // ---- Phase B identity: (unit ub, row rb) ----
    const int ub = tid & 63;
    const int rb = tid >> 6;
    float cst = 0.0f;

    // ---- stager identity (tid<156): x element (sr, si) ----
    const bool stg = (tid < ROWS*IN_);
    const int  sr  = stg ? (tid / IN_) : 0;
    const int  si  = stg ? (tid % IN_) : 0;

    // ---- head C1 identity (tid>=64): (output o1, k-quarter kc) ----
    const int i1 = tid - 64;                 // 0..191 when tid>=64
    const int o1 = (i1 >= 0) ? (i1 % 48) : 0;
    const int kc = (i1 >= 0) ? (i1 / 48) : 0;
    u64 cb2 = zero2;
    if (i1 >= 0 && kc == 0) { float b = b_out[o1]; cb2 = pack2(b, b); }
    // ---- head C2 identity (tid<48): output o2, all 4 rows ----
    const int o2 = tid;

    // ---- prologue ----
    for (int idx = tid; idx < 2*ROWS*KXP; idx += 256)
        ((float*)xs)[idx] = 0.0f;
    if (tid < H_) {
        #pragma unroll
        for (int r = 0; r < 4; r++) {
            hsT4[0][tid][r] = 0.0f;
            hsT4[1][tid][r] = 0.0f;
        }
    }
    for (int idx = tid; idx < H_*OUT_; idx += 256) {
        int k = idx / OUT_, o = idx % OUT_;
        woS[k][o] = W_out[o*H_ + k];
    }
    __syncthreads();
    if (stg) xs[0][sr][si] = x[((size_t)(row0 + sr) * T_) * IN_ + si];
    __syncthreads();

    float xnext = 0.0f;
    for (int t = 0; t < T_; t++) {
        const int wb = t & 1;        // B writes hsT4[wb]; C1 writes pc[wb]
        const int hb = wb ^ 1;       // A + C1 read hsT4[hb]; C2 reads pc[hb]
        const bool pf = stg && (t + 1 < T_);
        if (pf) xnext = x[((size_t)(row0 + sr) * T_ + (t + 1)) * IN_ + si];

        // ---- Phase A: gates(t) = W_hh·h(t-1) + W_ih·x(t) + b, into pq ----
        {
            u64 a01[4] = {zero2, zero2, zero2, zero2};
            u64 a23[4] = {zero2, zero2, zero2, zero2};
            const ulonglong2* hp = (const ulonglong2*)hsT4[hb] + ks*16;
            #pragma unroll
            for (int j = 0; j < 16; j++) {
                ulonglong2 q = hp[j];        // .x=(r0,r1) .y=(r2,r3)
                #pragma unroll
                for (int c = 0; c < 4; c++) {
                    a01[c] = fma2(wA[c][j], q.x, a01[c]);
                    a23[c] = fma2(wA[c][j], q.y, a23[c]);
                }
            }
            float hv[4][4];
            #pragma unroll
            for (int c = 0; c < 4; c++) {
                unpack2(a01[c], hv[c][0], hv[c][1]);
                unpack2(a23[c], hv[c][2], hv[c][3]);
            }
            #pragma unroll
            for (int r = 0; r < 4; r++) {
                u64 axr[4];
                #pragma unroll
                for (int c = 0; c < 4; c++) axr[c] = bias2c[c];
                const ulonglong2* xp = (const ulonglong2*)xs[wb][r] + ks*3;
                #pragma unroll
                for (int m = 0; m < 3; m++) {
                    ulonglong2 q = xp[m];
                    #pragma unroll
                    for (int c = 0; c < 4; c++) {
                        axr[c] = fma2(wx[c][2*m    ], q.x, axr[c]);
                        axr[c] = fma2(wx[c][2*m + 1], q.y, axr[c]);
                    }
                }
                #pragma unroll
                for (int c = 0; c < 4; c++) {
                    float e, f; unpack2(axr[c], e, f);
                    pq[ks][c][r][ua] = hv[c][r] + (e + f);
                }
            }
        }
        __syncthreads();   // bar1

        // ==== B-window: C2(t-2) | B(t) | C1(t-1) all overlapped ====

        // ---- head C2: emit y(t-2) from pc[hb] (tid<48) ----
        if (tid < 48 && t >= 2) {
            u64 s01 = add2(add2(pc[hb][0][0][o2], pc[hb][1][0][o2]),
                           add2(pc[hb][2][0][o2], pc[hb][3][0][o2]));
            u64 s23 = add2(add2(pc[hb][0][1][o2], pc[hb][1][1][o2]),
                           add2(pc[hb][2][1][o2], pc[hb][3][1][o2]));
            float z0, z1, z2, z3;
            unpack2(s01, z0, z1);
            unpack2(s23, z2, z3);
            const size_t tb = (size_t)(t - 2) * OUT_ + o2;
            out[(size_t)(row0    ) * T_ * OUT_ + tb] = sigm(z0);
            out[(size_t)(row0 + 1) * T_ * OUT_ + tb] = sigm(z1);
            out[(size_t)(row0 + 2) * T_ * OUT_ + tb] = sigm(z2);
            out[(size_t)(row0 + 3) * T_ * OUT_ + tb] = sigm(z3);
        }

        // ---- Phase B: sum partials, activations, write h(t) -> hsT4[wb] ----
        {
            float si_ = (pq[0][0][rb][ub] + pq[1][0][rb][ub])
                      + (pq[2][0][rb][ub] + pq[3][0][rb][ub]);
            float sf_ = (pq[0][1][rb][ub] + pq[1][1][rb][ub])
                      + (pq[2][1][rb][ub] + pq[3][1][rb][ub]);
            float sg_ = (pq[0][2][rb][ub] + pq[1][2][rb][ub])
                      + (pq[2][2][rb][ub] + pq[3][2][rb][ub]);
            float so_ = (pq[0][3][rb][ub] + pq[1][3][rb][ub])
                      + (pq[2][3][rb][ub] + pq[3][3][rb][ub]);
            float iv = sigm(si_), fv = sigm(sf_);
            float gv = tanh_(sg_), ov = sigm(so_);
            cst = fv * cst + iv * gv;
            hsT4[wb][ub][rb] = ov * tanh_(cst);
        }

        // ---- head C1: partials of head(h(t-1)) from hsT4[hb] -> pc[wb] ----
        if (i1 >= 0 && t >= 1) {
            u64 a01 = cb2, a23 = cb2;
            const ulonglong2* hp = (const ulonglong2*)hsT4[hb] + kc*16;
            #pragma unroll
            for (int j = 0; j < 16; j++) {
                ulonglong2 q = hp[j];
                float wv = woS[kc*16 + j][o1];
                u64 w2 = pack2(wv, wv);
                a01 = fma2(w2, q.x, a01);
                a23 = fma2(w2, q.y, a23);
            }
            pc[wb][kc][0][o1] = a01;
            pc[wb][kc][1][o1] = a23;
        }

        if (pf) xs[wb ^ 1][sr][si] = xnext;   // publish x(t+1)
        __syncthreads();   // bar2
    }

    // ---- epilogue: head of h(999), then emit y(998), y(999) ----
    // loop ended at bar2 of t=999; h(999) is in hsT4[1], pc[1] holds head(h(998)).
    if (i1 >= 0) {
        u64 a01 = cb2, a23 = cb2;
        const ulonglong2* hp = (const ulonglong2*)hsT4[1] + kc*16;
        #pragma unroll
        for (int j = 0; j < 16; j++) {
            ulonglong2 q = hp[j];
            float wv = woS[kc*16 + j][o1];
            u64 w2 = pack2(wv, wv);
            a01 = fma2(w2, q.x, a01);
            a23 = fma2(w2, q.y, a23);
        }
        pc[0][kc][0][o1] = a01;
        pc[0][kc][1][o1] = a23;
    }
    __syncthreads();
    if (tid < 48) {
        #pragma unroll
        for (int e = 0; e < 2; e++) {        // e=0: y(998) from pc[1]; e=1: y(999) from pc[0]
            const int pb = 1 - e;
            const int ts = 998 + e;
            u64 s01 = add2(add2(pc[pb][0][0][o2], pc[pb][1][0][o2]),
                           add2(pc[pb][2][0][o2], pc[pb][3][0][o2]));
            u64 s23 = add2(add2(pc[pb][0][1][o2], pc[pb][1][1][o2]),
                           add2(pc[pb][2][1][o2], pc[pb][3][1][o2]));
            float z0, z1, z2, z3;
            unpack2(s01, z0, z1);
            unpack2(s23, z2, z3);
            const size_t tb = (size_t)ts * OUT_ + o2;
            out[(size_t)(row0    ) * T_ * OUT_ + tb] = sigm(z0);
            out[(size_t)(row0 + 1) * T_ * OUT_ + tb] = sigm(z1);
            out[(size_t)(row0 + 2) * T_ * OUT_ + tb] = sigm(z2);
            out[(size_t)(row0 + 3) * T_ * OUT_ + tb] = sigm(z3);
        }
    }
}

extern "C" void kernel_launch(void* const* d_in, const int* in_sizes, int n_in,
                              void* d_out, int out_size)
{
    (void)in_sizes; (void)n_in; (void)out_size;
    const float* x     = (const float*)d_in[0];
    const float* W_ih  = (const float*)d_in[1];
    const float* W_hh  = (const float*)d_in[2];
    const float* b_ih  = (const float*)d_in[3];
    const float* b_hh  = (const float*)d_in[4];
    const float* W_out = (const float*)d_in[5];
    const float* b_out = (const float*)d_in[6];
    float* out = (float*)d_out;

    lstm_fused<<<CTAS, 256>>>(x, W_ih, W_hh, b_ih, b_hh, W_out, b_out, out);
}